// round 16
// baseline (speedup 1.0000x reference)
#include <cuda_runtime.h>
#include <cuda_bf16.h>
#include <math.h>
#include <stdint.h>

// Problem constants
#define CC    128
#define HWSZ  262144      // 512*512
#define BK    512         // B*K
#define NNEG  7
#define PP    4096
#define TAUI  (1.0f/0.07f)

// Tiling / grid roles
#define QTILE 64
#define PTILE 128
#define NPT   (PP/PTILE)  // 32
#define NGB   64          // gather blocks (ids 0..63)
#define NMB   256         // mma blocks   (ids 64..319) = 8 qtiles x 32 ptiles
#define NTOT  (NGB+NMB)   // 320

// smem layout (bytes): 272B row stride (256 data + 16 pad)
#define STRB    272
#define AH_OFF  0
#define AL_OFF  17408          // 64*272
#define BH_OFF  34816
#define BL_OFF  69632          // + 128*272
#define RN_OFF  104448         // + 128*272
#define PS_OFF  104960         // 2*128 floats (psum; reused as rowmax buf)
#define SMEM_T  105984

// Scratch (device globals — no allocation allowed)
__device__ __align__(256) float         g_pmax[BK*NPT];
__device__ __align__(256) float         g_nlog[BK*NNEG];
__device__ __align__(256) __nv_bfloat16 g_qh[BK*CC];
__device__ __align__(256) __nv_bfloat16 g_ql[BK*CC];
__device__ unsigned int g_qdone = 0;   // monotonic gather-arrival counter
__device__ unsigned int g_qready = 0;  // flag: this replay's gather complete (self-reset)
__device__ unsigned int g_c1 = 0;      // monotonic tail barrier counter

__device__ __forceinline__ uint32_t smem_u32(const void* p) {
    uint32_t a;
    asm("{ .reg .u64 t; cvta.to.shared.u64 t, %1; cvt.u32.u64 %0, t; }"
        : "=r"(a) : "l"(p));
    return a;
}

#define LDSM4(r0, r1, r2, r3, addr) \
    asm volatile("ldmatrix.sync.aligned.m8n8.x4.shared.b16 {%0,%1,%2,%3}, [%4];" \
        : "=r"(r0), "=r"(r1), "=r"(r2), "=r"(r3) : "r"(addr))

#define MMA16816(c, a0, a1, a2, a3, b0, b1) \
    asm volatile("mma.sync.aligned.m16n8k16.row.col.f32.bf16.bf16.f32 " \
        "{%0,%1,%2,%3}, {%4,%5,%6,%7}, {%8,%9}, {%0,%1,%2,%3};" \
        : "+f"((c)[0]), "+f"((c)[1]), "+f"((c)[2]), "+f"((c)[3]) \
        : "r"(a0), "r"(a1), "r"(a2), "r"(a3), "r"(b0), "r"(b1))

__device__ __forceinline__ uint32_t pack_hi(float a, float b) {
    __nv_bfloat16 h0 = __float2bfloat16(a);
    __nv_bfloat16 h1 = __float2bfloat16(b);
    return (uint32_t)__bfloat16_as_ushort(h0)
         | ((uint32_t)__bfloat16_as_ushort(h1) << 16);
}
__device__ __forceinline__ uint32_t pack_lo(float a, float b) {
    __nv_bfloat16 h0 = __float2bfloat16(a);
    __nv_bfloat16 h1 = __float2bfloat16(b);
    __nv_bfloat16 l0 = __float2bfloat16(a - __bfloat162float(h0));
    __nv_bfloat16 l1 = __float2bfloat16(b - __bfloat162float(h1));
    return (uint32_t)__bfloat16_as_ushort(l0)
         | ((uint32_t)__bfloat16_as_ushort(l1) << 16);
}

// ---------------------------------------------------------------------------
// Single launch.  grid=320, block=256, smem=106KB (2 blocks/SM).
//   ids [0,64):   gather blocks — warp-per-query gather+normalize+bf16 split;
//                 64th arrival sets g_qready (they never wait).
//   ids [64,320): mma blocks — stage B from fp32 pool (norms in-kernel),
//                 spin g_qready, stage A, mainloop, row max, neg logits,
//                 windowed tail barrier; blocks 64,65 do softmax CE -> out.
// ---------------------------------------------------------------------------
__global__ void __launch_bounds__(256, 2)
k_all(const float* __restrict__ qf,
      const float* __restrict__ pool,
      const int*   __restrict__ qidx,
      const float* __restrict__ neg,
      float* __restrict__ out) {
    extern __shared__ __align__(128) uint8_t smem[];
    __shared__ unsigned int s_old;
    __shared__ float sred[8];

    int bid  = blockIdx.x;
    int t    = threadIdx.x;
    int lane = t & 31;
    int wid  = t >> 5;

    // ================= gather role =================
    if (bid < NGB) {
        if (bid == 0 && t == 0) out[0] = 0.0f;
        int q   = bid * 8 + wid;
        int idx = qidx[q];
        int b   = q >> 6;
        const float* src = qf + ((size_t)(b * CC + lane)) * HWSZ + (size_t)idx;
        float v0 = src[0];
        float v1 = src[(size_t)32 * HWSZ];
        float v2 = src[(size_t)64 * HWSZ];
        float v3 = src[(size_t)96 * HWSZ];
        float ss = v0*v0 + v1*v1 + v2*v2 + v3*v3;
        #pragma unroll
        for (int o = 16; o; o >>= 1) ss += __shfl_xor_sync(0xffffffffu, ss, o);
        float inv = 1.0f / fmaxf(sqrtf(ss), 1e-12f);
        float nv[4] = {v0 * inv, v1 * inv, v2 * inv, v3 * inv};
        #pragma unroll
        for (int i = 0; i < 4; i++) {
            int c = lane + 32 * i;
            __nv_bfloat16 h = __float2bfloat16(nv[i]);
            g_qh[q * CC + c] = h;
            g_ql[q * CC + c] = __float2bfloat16(nv[i] - __bfloat162float(h));
        }
        __threadfence();
        __syncthreads();
        if (t == 0) {
            unsigned int old = atomicAdd(&g_qdone, 1u);
            if ((old & (NGB - 1u)) == NGB - 1u) {
                __threadfence();
                *((volatile unsigned int*)&g_qready) = 1u;
            }
            atomicAdd(&g_c1, 1u);   // tail arrive; gather blocks never wait
        }
        return;
    }

    // ================= mma role =================
    int flatm = bid - NGB;                 // 0..255
    int qbase = (flatm & 7) * QTILE;
    int ptile = flatm >> 3;                // 0..31
    int pbase = ptile * PTILE;
    float* ps = (float*)(smem + PS_OFF);
    float* rn = (float*)(smem + RN_OFF);

    // ---- stage B from fp32 pool: sumsq + bf16 hi/lo split (gather-independent) ----
    {
        int row = t >> 1, h = t & 1;
        const float4* src = (const float4*)(pool + (size_t)(pbase + row) * CC + h * 64);
        float ss = 0.0f;
        #pragma unroll
        for (int i = 0; i < 4; i++) {
            float4 a = src[i*4+0], b4 = src[i*4+1], c4 = src[i*4+2], d4 = src[i*4+3];
            ss += a.x*a.x + a.y*a.y + a.z*a.z + a.w*a.w
                + b4.x*b4.x + b4.y*b4.y + b4.z*b4.z + b4.w*b4.w
                + c4.x*c4.x + c4.y*c4.y + c4.z*c4.z + c4.w*c4.w
                + d4.x*d4.x + d4.y*d4.y + d4.z*d4.z + d4.w*d4.w;
            uint4 hA = make_uint4(pack_hi(a.x,a.y),  pack_hi(a.z,a.w),
                                  pack_hi(b4.x,b4.y), pack_hi(b4.z,b4.w));
            uint4 hB = make_uint4(pack_hi(c4.x,c4.y), pack_hi(c4.z,c4.w),
                                  pack_hi(d4.x,d4.y), pack_hi(d4.z,d4.w));
            uint4 lA = make_uint4(pack_lo(a.x,a.y),  pack_lo(a.z,a.w),
                                  pack_lo(b4.x,b4.y), pack_lo(b4.z,b4.w));
            uint4 lB = make_uint4(pack_lo(c4.x,c4.y), pack_lo(c4.z,c4.w),
                                  pack_lo(d4.x,d4.y), pack_lo(d4.z,d4.w));
            uint8_t* dsth = smem + BH_OFF + row * STRB + h * 128 + i * 32;
            uint8_t* dstl = smem + BL_OFF + row * STRB + h * 128 + i * 32;
            ((uint4*)dsth)[0] = hA; ((uint4*)dsth)[1] = hB;
            ((uint4*)dstl)[0] = lA; ((uint4*)dstl)[1] = lB;
        }
        ps[h * 128 + row] = ss;
    }
    __syncthreads();
    if (t < 128) rn[t] = 1.0f / fmaxf(sqrtf(ps[t] + ps[128 + t]), 1e-12f);

    // ---- wait for gather completion ----
    if (t == 0) {
        while (*((volatile unsigned int*)&g_qready) == 0u) { }
    }
    __syncthreads();
    __threadfence();   // acquire g_qh / g_ql

    // ---- stage A (queries hi/lo, already bf16) ----
    {
        int row = t >> 2, qt = t & 3;
        const uint4* sh = (const uint4*)((const char*)(g_qh + (size_t)(qbase + row) * CC) + qt * 64);
        const uint4* sl = (const uint4*)((const char*)(g_ql + (size_t)(qbase + row) * CC) + qt * 64);
        uint4* dh = (uint4*)(smem + AH_OFF + row * STRB + qt * 64);
        uint4* dl = (uint4*)(smem + AL_OFF + row * STRB + qt * 64);
        #pragma unroll
        for (int i = 0; i < 4; i++) { dh[i] = sh[i]; dl[i] = sl[i]; }
    }
    __syncthreads();

    // ---- mainloop: warp = (m-tile wid&3) x (n-half wid>>2) ----
    uint32_t sb = smem_u32(smem);
    int m0    = (wid & 3) * 16;
    int nhalf = wid >> 2;
    uint32_t aoff = (uint32_t)((m0 + (lane & 15)) * STRB + ((lane & 16) ? 16 : 0));
    uint32_t brow = (uint32_t)(nhalf * 64 + (lane & 7) + ((lane & 16) ? 8 : 0));
    uint32_t boff = brow * STRB + ((lane & 8) ? 16 : 0);
    uint32_t aAh = sb + AH_OFF + aoff;
    uint32_t aAl = sb + AL_OFF + aoff;
    uint32_t bBh = sb + BH_OFF + boff;
    uint32_t bBl = sb + BL_OFF + boff;

    float acc[8][4];
    #pragma unroll
    for (int i = 0; i < 8; i++)
        #pragma unroll
        for (int j = 0; j < 4; j++) acc[i][j] = 0.0f;

    #pragma unroll
    for (int ks = 0; ks < 8; ks++) {
        uint32_t kb = ks * 32;
        uint32_t ah0, ah1, ah2, ah3, al0, al1, al2, al3;
        LDSM4(ah0, ah1, ah2, ah3, aAh + kb);
        LDSM4(al0, al1, al2, al3, aAl + kb);
        #pragma unroll
        for (int j = 0; j < 4; j++) {
            uint32_t bh0, bh1, bh2, bh3, bl0, bl1, bl2, bl3;
            LDSM4(bh0, bh1, bh2, bh3, bBh + j * 16 * STRB + kb);
            LDSM4(bl0, bl1, bl2, bl3, bBl + j * 16 * STRB + kb);
            MMA16816(acc[2*j],   ah0, ah1, ah2, ah3, bh0, bh1);
            MMA16816(acc[2*j],   ah0, ah1, ah2, ah3, bl0, bl1);
            MMA16816(acc[2*j],   al0, al1, al2, al3, bh0, bh1);
            MMA16816(acc[2*j+1], ah0, ah1, ah2, ah3, bh2, bh3);
            MMA16816(acc[2*j+1], ah0, ah1, ah2, ah3, bl2, bl3);
            MMA16816(acc[2*j+1], al0, al1, al2, al3, bh2, bh3);
        }
    }

    // ---- row max over this warp's 64 protos, combine halves via smem ----
    {
        float mx1 = -3e38f, mx2 = -3e38f;
        #pragma unroll
        for (int nb = 0; nb < 8; nb++) {
            int n = nhalf * 64 + nb * 8 + 2 * (lane & 3);
            float r0 = rn[n], r1 = rn[n + 1];
            mx1 = fmaxf(mx1, fmaxf(acc[nb][0] * r0, acc[nb][1] * r1));
            mx2 = fmaxf(mx2, fmaxf(acc[nb][2] * r0, acc[nb][3] * r1));
        }
        #pragma unroll
        for (int o = 1; o <= 2; o <<= 1) {
            mx1 = fmaxf(mx1, __shfl_xor_sync(0xffffffffu, mx1, o));
            mx2 = fmaxf(mx2, __shfl_xor_sync(0xffffffffu, mx2, o));
        }
        __syncthreads();   // ps region free (rn already consumed? no: rn separate) — reuse ps as buf
        if ((lane & 3) == 0) {
            int r = lane >> 2;
            ps[nhalf * 64 + m0 + r]     = mx1;
            ps[nhalf * 64 + m0 + 8 + r] = mx2;
        }
        __syncthreads();
        if (t < 64) {
            float m = fmaxf(ps[t], ps[64 + t]);
            g_pmax[(qbase + t) * NPT + ptile] = m;
        }
    }

    // ---- negative logits: 2 queries per mma block (14 warp-dots) ----
    #pragma unroll
    for (int i = 0; i < 2; i++) {
        int pair = wid * 2 + i;
        if (pair < 2 * NNEG) {
            int q = flatm * 2 + pair / NNEG;
            int n = pair % NNEG;
            uint2 qh2 = *(const uint2*)((const char*)(g_qh + (size_t)q * CC + lane * 4));
            uint2 ql2 = *(const uint2*)((const char*)(g_ql + (size_t)q * CC + lane * 4));
            float4 nv = *(const float4*)(neg + ((size_t)q * NNEG + n) * CC + lane * 4);
            float qv[4];
            qv[0] = __bfloat162float(__ushort_as_bfloat16((unsigned short)(qh2.x & 0xffff)))
                  + __bfloat162float(__ushort_as_bfloat16((unsigned short)(ql2.x & 0xffff)));
            qv[1] = __bfloat162float(__ushort_as_bfloat16((unsigned short)(qh2.x >> 16)))
                  + __bfloat162float(__ushort_as_bfloat16((unsigned short)(ql2.x >> 16)));
            qv[2] = __bfloat162float(__ushort_as_bfloat16((unsigned short)(qh2.y & 0xffff)))
                  + __bfloat162float(__ushort_as_bfloat16((unsigned short)(ql2.y & 0xffff)));
            qv[3] = __bfloat162float(__ushort_as_bfloat16((unsigned short)(qh2.y >> 16)))
                  + __bfloat162float(__ushort_as_bfloat16((unsigned short)(ql2.y >> 16)));
            float dp = qv[0]*nv.x + qv[1]*nv.y + qv[2]*nv.z + qv[3]*nv.w;
            float ss = nv.x*nv.x + nv.y*nv.y + nv.z*nv.z + nv.w*nv.w;
            #pragma unroll
            for (int o = 16; o; o >>= 1) {
                dp += __shfl_xor_sync(0xffffffffu, dp, o);
                ss += __shfl_xor_sync(0xffffffffu, ss, o);
            }
            if (lane == 0)
                g_nlog[q * NNEG + n] = dp / fmaxf(sqrtf(ss), 1e-12f) * TAUI;
        }
    }

    // ---- tail barrier (windowed, monotonic); blocks 64,65 do the final ----
    __threadfence();
    __syncthreads();
    if (t == 0) s_old = atomicAdd(&g_c1, 1u);
    __syncthreads();
    unsigned int old = s_old;
    if (t == 0 && (old % NTOT) == NTOT - 1u)
        *((volatile unsigned int*)&g_qready) = 0u;   // self-reset for next replay
    if (flatm >= 2) return;
    unsigned int tgt = old - (old % NTOT) + (unsigned int)NTOT;
    if (t == 0) {
        while (*((volatile unsigned int*)&g_c1) < tgt) { }
    }
    __syncthreads();
    __threadfence();   // acquire g_pmax / g_nlog / out-zero

    // ---- final: thread-per-query softmax CE, block reduce, atomicAdd ----
    {
        int q = flatm * 256 + t;
        float mx = -3e38f;
        #pragma unroll
        for (int j = 0; j < NPT; j++) mx = fmaxf(mx, g_pmax[q * NPT + j]);
        float l0 = mx * TAUI;

        float ln[NNEG];
        #pragma unroll
        for (int n = 0; n < NNEG; n++) ln[n] = g_nlog[q * NNEG + n];

        float m = l0;
        #pragma unroll
        for (int n = 0; n < NNEG; n++) m = fmaxf(m, ln[n]);
        float se = expf(l0 - m);
        #pragma unroll
        for (int n = 0; n < NNEG; n++) se += expf(ln[n] - m);
        float loss = logf(se) + m - l0;      // = -(log_softmax[0])

        #pragma unroll
        for (int o = 16; o; o >>= 1) loss += __shfl_xor_sync(0xffffffffu, loss, o);
        if (lane == 0) sred[wid] = loss;
        __syncthreads();
        if (t == 0) {
            float s = 0.0f;
            #pragma unroll
            for (int i = 0; i < 8; i++) s += sred[i];
            atomicAdd(out, s * (1.0f / (float)BK));
        }
    }
}

// ---------------------------------------------------------------------------
extern "C" void kernel_launch(void* const* d_in, const int* in_sizes, int n_in,
                              void* d_out, int out_size) {
    const float* qf   = (const float*)d_in[0];  // [8,128,512,512]
    const float* pool = (const float*)d_in[1];  // [4096,128]
    const float* neg  = (const float*)d_in[2];  // [8,64,7,128]
    const int*   qidx = (const int*)d_in[3];    // [8,64]
    float* out = (float*)d_out;

    cudaFuncSetAttribute(k_all, cudaFuncAttributeMaxDynamicSharedMemorySize, SMEM_T);

    k_all<<<NTOT, 256, SMEM_T>>>(qf, pool, qidx, neg, out);
}